// round 13
// baseline (speedup 1.0000x reference)
#include <cuda_runtime.h>
#include <math.h>

#define Bz 32
#define Hh 512
#define Vv 10000
#define Tt 20
#define Ss 49
#define G4 2048
#define NT_LOG 313          // 32-wide v tiles

// ---------------- device scratch ----------------
__device__ float g_keysT[Bz*Ss*Hh];      // [b][s][d]
__device__ float g_valsSD[Bz*Ss*Hh];     // [b][s][d]
__device__ float g_h[2*Bz*Hh];           // post-cell hidden
__device__ float g_hF[2*Bz*Hh];          // post-attention hidden (recurrent input)
__device__ float g_c[2*Bz*Hh];
__device__ float g_emb[Bz*Hh];
__device__ float g_q[2*Bz*Hh];
__device__ float g_attn[2*Bz*Hh];
__device__ float g_logits[Bz*Vv];
__device__ float g_gpart[8*Bz*G4];       // 8 k-slice partials, [(y*32+b)*2048 + c]
__device__ float g_WihP[2*512*G4];       // [l][k][c], c = x*64 + q*4 + gate
__device__ float g_WhhP[2*512*G4];
__device__ float g_projWT[Hh*Vv];        // [d][v]
__device__ float g_WqT[Hh*Hh];           // [k][d]
__device__ float g_hattWT[2*Hh*Hh];      // [k][d]
__device__ int   g_cnt[32];              // zero-init; reset by last block each use

__device__ __forceinline__ float sigm(float x) { return 1.0f / (1.0f + expf(-x)); }

__device__ __forceinline__ void ffma2(unsigned long long &d, unsigned long long a,
                                      unsigned long long b) {
    asm("fma.rn.f32x2 %0, %1, %2, %0;" : "+l"(d) : "l"(a), "l"(b));
}
__device__ __forceinline__ unsigned long long bcast2(float w) {
    unsigned long long r;
    asm("mov.b64 %0, {%1, %1};" : "=l"(r) : "f"(w));
    return r;
}

// ================= PREP =================

// projW + Wq + hattW transposes (5776 32x32-tile tasks)
__global__ void prep_transposes(const float* __restrict__ projW, const float* __restrict__ Wq,
                                const float* __restrict__ hattW) {
    __shared__ float tile[32][33];
    int tx = threadIdx.x & 31, ty = threadIdx.x >> 5;
    for (int task = blockIdx.x; task < 5776; task += gridDim.x) {
        const float* src; float* dst; int R, C, bx, by;
        if (task < 5008)      { src = projW;         dst = g_projWT;  R = Vv; C = Hh;   bx = task % 16; by = task / 16; }
        else if (task < 5264) { int u = task - 5008; src = Wq;        dst = g_WqT;     R = Hh; C = Hh;   bx = u % 16; by = u / 16; }
        else                  { int u = task - 5264; src = hattW;     dst = g_hattWT;  R = Hh; C = 2*Hh; bx = u % 32; by = u / 32; }
        for (int i = 0; i < 32; i += 8) {
            int r = by*32 + ty + i, c = bx*32 + tx;
            if (r < R && c < C) tile[ty + i][tx] = src[r*C + c];
        }
        __syncthreads();
        for (int i = 0; i < 32; i += 8) {
            int r = by*32 + tx, c = bx*32 + ty + i;
            if (r < R && c < C) dst[c*R + r] = tile[tx][ty + i];
        }
        __syncthreads();
    }
}

// gate-weight reorder: dst[l][k][c], c = x*64 + q*4 + g  ->  src row g*512 + x*16 + q
__global__ void prep_reorder(const float* __restrict__ Wih, const float* __restrict__ Whh) {
    int id = blockIdx.x * 256 + threadIdx.x;     // 2*2*512*2048 = 4194304
    int c = id & 2047;
    int k = (id >> 11) & 511;
    int l = (id >> 20) & 1;
    int part = id >> 21;
    int x = c >> 6, cc = c & 63;
    int q = cc >> 2, g = cc & 3;
    int row = g*512 + x*16 + q;
    const float* src = part ? Whh : Wih;
    float v = src[(l*G4 + row)*512 + k];
    float* dst = part ? g_WhhP : g_WihP;
    dst[(l*512 + k)*G4 + c] = v;
}

__global__ void prep_kv(const float* __restrict__ chan,
                        const float* __restrict__ Wk, const float* __restrict__ bk,
                        const float* __restrict__ Wv, const float* __restrict__ bv) {
    int id = blockIdx.x * 256 + threadIdx.x;
    int d = id & 511;
    int r = id >> 9;
    int s = r % Ss;
    int b = r / Ss;
    const float* cp  = &chan[(b*Hh + d)*Ss];
    const float* wkp = &Wk[s*Ss];
    const float* wvp = &Wv[s*Ss];
    float aK = bk[s], aV = bv[s];
#pragma unroll
    for (int k = 0; k < Ss; k++) { float c = cp[k]; aK += c*wkp[k]; aV += c*wvp[k]; }
    g_keysT[(b*Ss + s)*Hh + d]  = tanhf(aK);
    g_valsSD[(b*Ss + s)*Hh + d] = tanhf(aV);
}

__global__ void prep_init_t0(const float* __restrict__ pooled, const float* __restrict__ embed,
                             const int* __restrict__ sos, const float* __restrict__ projb,
                             float* __restrict__ res) {
    int blk = blockIdx.x, tid = threadIdx.x;
    if (blk < 40) {
        int v = blk*256 + tid;
        if (v < Vv) {
            int sv = sos[0];
            float acc = projb[v];
            for (int d = 0; d < Hh; d++) acc += embed[sv*Hh + d] * g_projWT[d*Vv + v];
            for (int b = 0; b < Bz; b++) res[b*(Vv*Tt) + v*Tt] = acc;
        }
    } else {
        int i = (blk - 40)*256 + tid;
        int d = i & (Hh - 1);
        g_emb[i] = embed[sos[0]*Hh + d];
        float p = pooled[i];
        g_hF[i] = p; g_hF[Bz*Hh + i] = p;
        g_c[i]  = p; g_c[Bz*Hh + i]  = p;
    }
}

// ================= q-GEMM body =================
__device__ void q_body(int l, int qb, float* sH, const float* __restrict__ bq) {
    int tid = threadIdx.x;
    const float4* h4 = (const float4*)(g_h + l*Bz*Hh);
    float4* s4 = (float4*)sH;
    for (int i = tid; i < Bz*Hh/4; i += 256) s4[i] = h4[i];
    __syncthreads();

    int lane = tid & 31, bg = tid >> 5;
    int d = qb*32 + lane;
    float acc0 = 0.f, acc1 = 0.f, acc2 = 0.f, acc3 = 0.f;
    const float* a0 = &sH[(bg*4 + 0)*Hh];
    const float* a1 = &sH[(bg*4 + 1)*Hh];
    const float* a2 = &sH[(bg*4 + 2)*Hh];
    const float* a3 = &sH[(bg*4 + 3)*Hh];
#pragma unroll 8
    for (int k = 0; k < Hh; k += 4) {
        const float* wp = &g_WqT[k*Hh + d];
        float w0 = wp[0], w1 = wp[Hh], w2 = wp[2*Hh], w3 = wp[3*Hh];
        float4 v0 = *(const float4*)&a0[k];
        float4 v1 = *(const float4*)&a1[k];
        float4 v2 = *(const float4*)&a2[k];
        float4 v3 = *(const float4*)&a3[k];
        acc0 += v0.x*w0 + v0.y*w1 + v0.z*w2 + v0.w*w3;
        acc1 += v1.x*w0 + v1.y*w1 + v1.z*w2 + v1.w*w3;
        acc2 += v2.x*w0 + v2.y*w1 + v2.z*w2 + v2.w*w3;
        acc3 += v3.x*w0 + v3.y*w1 + v3.z*w2 + v3.w*w3;
    }
    float bv = bq[d];
    g_q[(l*Bz + bg*4 + 0)*Hh + d] = tanhf(acc0 + bv);
    g_q[(l*Bz + bg*4 + 1)*Hh + d] = tanhf(acc1 + bv);
    g_q[(l*Bz + bg*4 + 2)*Hh + d] = tanhf(acc2 + bv);
    g_q[(l*Bz + bg*4 + 3)*Hh + d] = tanhf(acc3 + bv);
}

// ================= gates + FUSED cell: 256 blocks (32 j-chunks x 8 k-slices) =================
__global__ __launch_bounds__(256) void gatescell_kernel(int l, const float* __restrict__ bih,
                                                        const float* __restrict__ bhh) {
    extern __shared__ float S[];
    __shared__ int s_last;
    int tid = threadIdx.x, blk = blockIdx.x;
    int x = blk & 31, y = blk >> 5;          // x: 64-c chunk, y: 128-k slice
    int ihPart = (y < 4);
    int kbase = (y & 3) * 128;
    const float* src = ihPart ? ((l == 0) ? g_emb : g_h) : (g_hF + l*Bz*Hh);
    float* sh = S;                            // [32 b][128 k]
    for (int i = tid; i < 32*128; i += 256) {
        int b = i >> 7, kk = i & 127;
        sh[b*128 + kk] = src[b*Hh + kbase + kk];
    }
    __syncthreads();

    const float* WT = (ihPart ? g_WihP : g_WhhP) + l*512*G4;
    int jl = tid & 63, bg = tid >> 6;
    int j = x*64 + jl;

    float acc0=0,acc1=0,acc2=0,acc3=0,acc4=0,acc5=0,acc6=0,acc7=0;
    const float* shb = &sh[bg*8*128];
#pragma unroll 8
    for (int mi = 0; mi < 128; mi += 4) {
        const float* wp = &WT[(kbase + mi)*G4 + j];
        float w0 = wp[0], w1 = wp[G4], w2 = wp[2*G4], w3 = wp[3*G4];
        float4 v0 = *(const float4*)&shb[0*128 + mi];
        float4 v1 = *(const float4*)&shb[1*128 + mi];
        float4 v2 = *(const float4*)&shb[2*128 + mi];
        float4 v3 = *(const float4*)&shb[3*128 + mi];
        float4 v4 = *(const float4*)&shb[4*128 + mi];
        float4 v5 = *(const float4*)&shb[5*128 + mi];
        float4 v6 = *(const float4*)&shb[6*128 + mi];
        float4 v7 = *(const float4*)&shb[7*128 + mi];
        acc0 += v0.x*w0 + v0.y*w1 + v0.z*w2 + v0.w*w3;
        acc1 += v1.x*w0 + v1.y*w1 + v1.z*w2 + v1.w*w3;
        acc2 += v2.x*w0 + v2.y*w1 + v2.z*w2 + v2.w*w3;
        acc3 += v3.x*w0 + v3.y*w1 + v3.z*w2 + v3.w*w3;
        acc4 += v4.x*w0 + v4.y*w1 + v4.z*w2 + v4.w*w3;
        acc5 += v5.x*w0 + v5.y*w1 + v5.z*w2 + v5.w*w3;
        acc6 += v6.x*w0 + v6.y*w1 + v6.z*w2 + v6.w*w3;
        acc7 += v7.x*w0 + v7.y*w1 + v7.z*w2 + v7.w*w3;
    }
    int bb = bg*8;
    float* gp = &g_gpart[(y*32)*G4 + j];
    gp[(bb+0)*G4] = acc0; gp[(bb+1)*G4] = acc1;
    gp[(bb+2)*G4] = acc2; gp[(bb+3)*G4] = acc3;
    gp[(bb+4)*G4] = acc4; gp[(bb+5)*G4] = acc5;
    gp[(bb+6)*G4] = acc6; gp[(bb+7)*G4] = acc7;

    // ---- last-block fused cell ----
    __threadfence();                       // make this thread's partials visible
    __syncthreads();
    if (tid == 0) {
        int old = atomicAdd(&g_cnt[x], 1);
        s_last = (old == 7) ? 1 : 0;
        if (old == 7) g_cnt[x] = 0;        // reset for next use (this launch's last arriver)
    }
    __syncthreads();
    if (!s_last) return;
    __threadfence();                       // L1 invalidate: see other blocks' partials

    int c_l = tid & 63, bh2 = tid >> 6;
    float tot[8];
#pragma unroll
    for (int j2 = 0; j2 < 8; j2++) tot[j2] = 0.f;
    for (int yy = 0; yy < 8; yy++) {
        const float* gp2 = &g_gpart[(yy*32 + bh2*8)*G4 + x*64 + c_l];
#pragma unroll
        for (int j2 = 0; j2 < 8; j2++) tot[j2] += gp2[j2*G4];
    }
    float* sc = S;                          // reuse smem: [32 b][64 c]
    __syncthreads();
#pragma unroll
    for (int j2 = 0; j2 < 8; j2++) sc[(bh2*8 + j2)*64 + c_l] = tot[j2];
    __syncthreads();
#pragma unroll
    for (int rep = 0; rep < 2; rep++) {
        int idx = rep*256 + tid;
        int q = idx >> 5, b = idx & 31;
        int gi = x*16 + q;
        const float* bi = bih + l*G4; const float* bhp = bhh + l*G4;
        const float* scb = &sc[b*64 + q*4];
        float vi = scb[0] + bi[gi]        + bhp[gi];
        float vf = scb[1] + bi[512 + gi]  + bhp[512 + gi];
        float vg = scb[2] + bi[1024 + gi] + bhp[1024 + gi];
        float vo = scb[3] + bi[1536 + gi] + bhp[1536 + gi];
        int id2 = (l*Bz + b)*Hh + gi;
        float c = g_c[id2];
        float cn = sigm(vf)*c + sigm(vi)*tanhf(vg);
        g_c[id2] = cn;
        g_h[id2] = sigm(vo)*tanhf(cn);
    }
}

// gatescell(l=1) blocks 0..255 || q0 blocks 256..271
__global__ __launch_bounds__(256) void gc1_q0_kernel(const float* __restrict__ bih,
                                                     const float* __restrict__ bhh,
                                                     const float* __restrict__ bq);

// ================= attention body (softmax + attn vector for 2 batches) =================
__device__ void att_body(int l, int b0, float* S) {
    int tid = threadIdx.x;
    float* sq   = S;            // [2][512]
    float* ssc  = S + 1024;
    float* sw   = S + 1152;
    float* smax = S + 1280;
    float* sinv = S + 1284;
    for (int i = tid; i < 2*Hh; i += 256) {
        int bb = i >> 9;
        sq[i] = g_q[(l*Bz + b0 + bb)*Hh + (i & 511)];
    }
    __syncthreads();

    int warp = tid >> 5, lane = tid & 31;
    int half = warp >> 2, w2 = warp & 3;
    int b = b0 + half;
    for (int s = w2; s < Ss; s += 4) {
        const float* kp = &g_keysT[(b*Ss + s)*Hh];
        const float* qp = &sq[half*Hh];
        float p = 0.f;
        for (int d = lane; d < Hh; d += 32) p += qp[d]*kp[d];
#pragma unroll
        for (int o = 16; o; o >>= 1) p += __shfl_xor_sync(0xffffffffu, p, o);
        if (lane == 0) ssc[half*64 + s] = p * (1.0f/7.0f);
    }
    __syncthreads();
    if (tid < 2) {
        float mx = -INFINITY;
        for (int s = 0; s < Ss; s++) mx = fmaxf(mx, ssc[tid*64 + s]);
        smax[tid] = mx;
    }
    __syncthreads();
    if (tid < 128) {
        int bb = tid >> 6, s = tid & 63;
        if (s < Ss) sw[bb*64 + s] = expf(ssc[bb*64 + s] - smax[bb]);
    }
    __syncthreads();
    if (tid < 2) {
        float sum = 0.f;
        for (int s = 0; s < Ss; s++) sum += sw[tid*64 + s];
        sinv[tid] = 1.0f / sum;
    }
    __syncthreads();
#pragma unroll
    for (int rep = 0; rep < 4; rep++) {
        int idx = rep*256 + tid;
        int bb = idx >> 9, d = idx & 511;
        const float* wv = &sw[bb*64];
        float a = 0.f;
#pragma unroll
        for (int s = 0; s < Ss; s++)
            a += wv[s] * g_valsSD[((b0 + bb)*Ss + s)*Hh + d];
        g_attn[(l*Bz + b0 + bb)*Hh + d] = a * sinv[bb];
    }
}

// ================= logits: f32x2 body =================
__device__ void logits_body(int tile, float* shl, const float* __restrict__ projb,
                            float* __restrict__ res, int t) {
    int tid = threadIdx.x;
    // pair-interleaved: shl[bp*1024 + d*2 + half]
    const float4* H4 = (const float4*)(g_h + Bz*Hh);
    for (int i = tid; i < Bz*Hh/4; i += 256) {
        float4 v = H4[i];
        int b = i >> 7;
        int d0 = (i & 127) << 2;
        float* dst = &shl[(b >> 1)*1024 + (b & 1)];
        dst[(d0+0)*2] = v.x; dst[(d0+1)*2] = v.y;
        dst[(d0+2)*2] = v.z; dst[(d0+3)*2] = v.w;
    }
    __syncthreads();

    int vl = tid & 31, bg = tid >> 5;
    int v = tile*32 + vl;
    int vc = (v < Vv) ? v : (Vv - 1);
    const ulonglong2* p0 = (const ulonglong2*)&shl[(bg*2 + 0)*1024];
    const ulonglong2* p1 = (const ulonglong2*)&shl[(bg*2 + 1)*1024];
    unsigned long long acc0 = 0ull, acc1 = 0ull;   // (0.0f, 0.0f)
#pragma unroll 8
    for (int d = 0; d < Hh; d += 2) {
        float w0 = g_projWT[d*Vv + vc];
        float w1 = g_projWT[(d+1)*Vv + vc];
        unsigned long long ww0 = bcast2(w0), ww1 = bcast2(w1);
        ulonglong2 ua = p0[d >> 1];
        ulonglong2 ub = p1[d >> 1];
        ffma2(acc0, ua.x, ww0); ffma2(acc0, ua.y, ww1);
        ffma2(acc1, ub.x, ww0); ffma2(acc1, ub.y, ww1);
    }
    if (v < Vv) {
        float pb = projb[v];
        float r0, r1, r2, r3;
        asm("mov.b64 {%0, %1}, %2;" : "=f"(r0), "=f"(r1) : "l"(acc0));
        asm("mov.b64 {%0, %1}, %2;" : "=f"(r2), "=f"(r3) : "l"(acc1));
        float rr[4] = {r0 + pb, r1 + pb, r2 + pb, r3 + pb};
#pragma unroll
        for (int i = 0; i < 4; i++) {
            int b = bg*4 + i;
            g_logits[b*Vv + v] = rr[i];
            res[b*(Vv*Tt) + v*Tt + t] = rr[i];
        }
    }
}

// logits blocks 0..312 || q1 blocks 313..328 || att0 blocks 329..344
__global__ __launch_bounds__(256) void logits_q1_att0_kernel(const float* __restrict__ projb,
                                                             float* __restrict__ res, int t,
                                                             const float* __restrict__ bq) {
    extern __shared__ float S[];
    int blk = blockIdx.x;
    if (blk < NT_LOG)       logits_body(blk, S, projb, res, t);
    else if (blk < NT_LOG + 16) q_body(1, blk - NT_LOG, S, bq);
    else                    att_body(0, (blk - NT_LOG - 16)*2, S);
}

// ================= argmax body =================
__device__ void argmax_body(int b, float* S, const float* __restrict__ embed) {
    float* sv = S;
    int* si = (int*)(S + 256);
    int tid = threadIdx.x;
    float best = -INFINITY; int bi = 0;
    for (int v = tid; v < Vv; v += 256) {
        float x = g_logits[b*Vv + v];
        if (x > best) { best = x; bi = v; }
    }
    sv[tid] = best; si[tid] = bi;
    __syncthreads();
    for (int s = 128; s > 0; s >>= 1) {
        if (tid < s) {
            float ov = sv[tid + s]; int oi = si[tid + s];
            if (ov > sv[tid] || (ov == sv[tid] && oi < si[tid])) { sv[tid] = ov; si[tid] = oi; }
        }
        __syncthreads();
    }
    int widx = si[0];
    for (int d = tid; d < Hh; d += 256)
        g_emb[b*Hh + d] = embed[widx*Hh + d];
}

// ================= hatt body =================
__device__ void hatt_body(int l, int rb, float* S, const float* __restrict__ hattb) {
    float* sX = S;               // [8][1024]
    float* sred = S + 8*1024;    // [256][8]
    int tid = threadIdx.x;
    int dg = rb >> 2, bq4 = rb & 3;
    int b0 = bq4*8;
    for (int i = tid; i < 8*1024; i += 256) {
        int b = i >> 10, kk = i & 1023;
        float v = (kk < 512) ? g_attn[(l*Bz + b0 + b)*Hh + kk]
                             : g_h[(l*Bz + b0 + b)*Hh + (kk - 512)];
        sX[i] = v;
    }
    __syncthreads();

    int lane = tid & 31, w = tid >> 5;
    int d = dg*32 + lane;
    float acc[8];
#pragma unroll
    for (int j = 0; j < 8; j++) acc[j] = 0.f;
    int k0 = w*128;
#pragma unroll 2
    for (int kk = k0; kk < k0 + 128; kk += 4) {
        const float* wp = &g_hattWT[kk*Hh + d];
        float w0 = wp[0], w1 = wp[Hh], w2 = wp[2*Hh], w3 = wp[3*Hh];
#pragma unroll
        for (int j = 0; j < 8; j++) {
            float4 a = *(const float4*)&sX[j*1024 + kk];
            acc[j] += a.x*w0 + a.y*w1 + a.z*w2 + a.w*w3;
        }
    }
#pragma unroll
    for (int j = 0; j < 8; j++) sred[(w*32 + lane)*8 + j] = acc[j];
    __syncthreads();

    int d_l = tid >> 3, j = tid & 7;
    float s = 0.f;
#pragma unroll
    for (int w2 = 0; w2 < 8; w2++) s += sred[(w2*32 + d_l)*8 + j];
    int dd = dg*32 + d_l;
    g_hF[(l*Bz + b0 + j)*Hh + dd] = tanhf(s + hattb[dd]);
}

// att1 blocks 0..15 || argmax blocks 16..47 || hatt0 blocks 48..111
__global__ __launch_bounds__(256) void att1_argmax_hatt0_kernel(const float* __restrict__ embed,
                                                                const float* __restrict__ hattb) {
    __shared__ float SS[8*1024 + 256*8];    // 40 KB (hatt worst case)
    int blk = blockIdx.x;
    if (blk < 16)      att_body(1, blk*2, SS);
    else if (blk < 48) argmax_body(blk - 16, SS, embed);
    else               hatt_body(0, blk - 48, SS, hattb);
}

__global__ __launch_bounds__(256) void hatt1_kernel(const float* __restrict__ hattb) {
    __shared__ float SS[8*1024 + 256*8];
    hatt_body(1, blockIdx.x, SS, hattb);
}

// gatescell(l=1) || q0 — defined after bodies
__global__ __launch_bounds__(256) void gc1_q0_kernel(const float* __restrict__ bih,
                                                     const float* __restrict__ bhh,
                                                     const float* __restrict__ bq) {
    extern __shared__ float S[];
    int blk = blockIdx.x;
    if (blk < 256) {
        // inline gatescell body for l=1 by calling the same code path:
        // replicate via function: see gatescell_body below
        // (implemented as device function to share with gatescell_kernel)
        extern __device__ void gatescell_body(int, const float*, const float*, float*);
        gatescell_body(1, bih, bhh, S);
    } else {
        q_body(0, blk - 256, S, bq);
    }
}

// shared gates+cell body (used by both launches)
__device__ void gatescell_body(int l, const float* __restrict__ bih,
                               const float* __restrict__ bhh, float* S) {
    __shared__ int s_last;
    int tid = threadIdx.x, blk = blockIdx.x;
    int x = blk & 31, y = blk >> 5;
    int ihPart = (y < 4);
    int kbase = (y & 3) * 128;
    const float* src = ihPart ? ((l == 0) ? g_emb : g_h) : (g_hF + l*Bz*Hh);
    float* sh = S;
    for (int i = tid; i < 32*128; i += 256) {
        int b = i >> 7, kk = i & 127;
        sh[b*128 + kk] = src[b*Hh + kbase + kk];
    }
    __syncthreads();

    const float* WT = (ihPart ? g_WihP : g_WhhP) + l*512*G4;
    int jl = tid & 63, bg = tid >> 6;
    int j = x*64 + jl;

    float acc0=0,acc1=0,acc2=0,acc3=0,acc4=0,acc5=0,acc6=0,acc7=0;
    const float* shb = &sh[bg*8*128];
#pragma unroll 8
    for (int mi = 0; mi < 128; mi += 4) {
        const float* wp = &WT[(kbase + mi)*G4 + j];
        float w0 = wp[0], w1 = wp[G4], w2 = wp[2*G4], w3 = wp[3*G4];
        float4 v0 = *(const float4*)&shb[0*128 + mi];
        float4 v1 = *(const float4*)&shb[1*128 + mi];
        float4 v2 = *(const float4*)&shb[2*128 + mi];
        float4 v3 = *(const float4*)&shb[3*128 + mi];
        float4 v4 = *(const float4*)&shb[4*128 + mi];
        float4 v5 = *(const float4*)&shb[5*128 + mi];
        float4 v6 = *(const float4*)&shb[6*128 + mi];
        float4 v7 = *(const float4*)&shb[7*128 + mi];
        acc0 += v0.x*w0 + v0.y*w1 + v0.z*w2 + v0.w*w3;
        acc1 += v1.x*w0 + v1.y*w1 + v1.z*w2 + v1.w*w3;
        acc2 += v2.x*w0 + v2.y*w1 + v2.z*w2 + v2.w*w3;
        acc3 += v3.x*w0 + v3.y*w1 + v3.z*w2 + v3.w*w3;
        acc4 += v4.x*w0 + v4.y*w1 + v4.z*w2 + v4.w*w3;
        acc5 += v5.x*w0 + v5.y*w1 + v5.z*w2 + v5.w*w3;
        acc6 += v6.x*w0 + v6.y*w1 + v6.z*w2 + v6.w*w3;
        acc7 += v7.x*w0 + v7.y*w1 + v7.z*w2 + v7.w*w3;
    }
    int bb = bg*8;
    float* gp = &g_gpart[(y*32)*G4 + j];
    gp[(bb+0)*G4] = acc0; gp[(bb+1)*G4] = acc1;
    gp[(bb+2)*G4] = acc2; gp[(bb+3)*G4] = acc3;
    gp[(bb+4)*G4] = acc4; gp[(bb+5)*G4] = acc5;
    gp[(bb+6)*G4] = acc6; gp[(bb+7)*G4] = acc7;

    __threadfence();
    __syncthreads();
    if (tid == 0) {
        int old = atomicAdd(&g_cnt[x], 1);
        s_last = (old == 7) ? 1 : 0;
        if (old == 7) g_cnt[x] = 0;
    }
    __syncthreads();
    if (!s_last) return;
    __threadfence();

    int c_l = tid & 63, bh2 = tid >> 6;
    float tot[8];
#pragma unroll
    for (int j2 = 0; j2 < 8; j2++) tot[j2] = 0.f;
    for (int yy = 0; yy < 8; yy++) {
        const float* gp2 = &g_gpart[(yy*32 + bh2*8)*G4 + x*64 + c_l];
#pragma unroll
        for (int j2 = 0; j2 < 8; j2++) tot[j2] += gp2[j2*G4];
    }
    float* sc = S;
    __syncthreads();
#pragma unroll
    for (int j2 = 0; j2 < 8; j2++) sc[(bh2*8 + j2)*64 + c_l] = tot[j2];
    __syncthreads();
#pragma unroll
    for (int rep = 0; rep < 2; rep++) {
        int idx = rep*256 + tid;
        int q = idx >> 5, b = idx & 31;
        int gi = x*16 + q;
        const float* bi = bih + l*G4; const float* bhp = bhh + l*G4;
        const float* scb = &sc[b*64 + q*4];
        float vi = scb[0] + bi[gi]        + bhp[gi];
        float vf = scb[1] + bi[512 + gi]  + bhp[512 + gi];
        float vg = scb[2] + bi[1024 + gi] + bhp[1024 + gi];
        float vo = scb[3] + bi[1536 + gi] + bhp[1536 + gi];
        int id2 = (l*Bz + b)*Hh + gi;
        float c = g_c[id2];
        float cn = sigm(vf)*c + sigm(vi)*tanhf(vg);
        g_c[id2] = cn;
        g_h[id2] = sigm(vo)*tanhf(cn);
    }
}

// ---------------- host launcher ----------------
extern "C" void kernel_launch(void* const* d_in, const int* in_sizes, int n_in,
                              void* d_out, int out_size) {
    const float* img    = (const float*)d_in[0];
    const float* pooled = (const float*)d_in[1];
    const float* embed  = (const float*)d_in[2];
    const float* Wq     = (const float*)d_in[3];
    const float* bq     = (const float*)d_in[4];
    const float* Wk     = (const float*)d_in[5];
    const float* bk     = (const float*)d_in[6];
    const float* Wv     = (const float*)d_in[7];
    const float* bv     = (const float*)d_in[8];
    const float* Wih    = (const float*)d_in[9];
    const float* Whh    = (const float*)d_in[10];
    const float* bih    = (const float*)d_in[11];
    const float* bhh    = (const float*)d_in[12];
    const float* projW  = (const float*)d_in[13];
    const float* projb  = (const float*)d_in[14];
    const float* hattW  = (const float*)d_in[15];
    const float* hattb  = (const float*)d_in[16];
    const int*   sos    = (const int*)d_in[17];
    float* res = (float*)d_out;

    const int big_smem = Bz * Hh * (int)sizeof(float);   // 64 KB
    cudaFuncSetAttribute(gatescell_kernel,      cudaFuncAttributeMaxDynamicSharedMemorySize, big_smem);
    cudaFuncSetAttribute(gc1_q0_kernel,         cudaFuncAttributeMaxDynamicSharedMemorySize, big_smem);
    cudaFuncSetAttribute(logits_q1_att0_kernel, cudaFuncAttributeMaxDynamicSharedMemorySize, big_smem);

    prep_transposes<<<592, 256>>>(projW, Wq, hattW);
    prep_reorder<<<16384, 256>>>(Wih, Whh);
    prep_kv<<<3136, 256>>>(img, Wk, bk, Wv, bv);
    prep_init_t0<<<104, 256>>>(pooled, embed, sos, projb, res);

    const int gate_smem = 32 * 128 * (int)sizeof(float);  // 16 KB
    for (int t = 0; t < Tt - 1; t++) {
        int withQ = (t < Tt - 2) ? 1 : 0;
        gatescell_kernel<<<256, 256, gate_smem>>>(0, bih, bhh);
        if (withQ) gc1_q0_kernel<<<272, 256, big_smem>>>(bih, bhh, bq);
        else       gc1_q0_kernel<<<256, 256, gate_smem>>>(bih, bhh, bq);
        logits_q1_att0_kernel<<<withQ ? (NT_LOG + 32) : NT_LOG, 256, big_smem>>>(projb, res, t + 1, bq);
        if (withQ) {
            att1_argmax_hatt0_kernel<<<112, 256>>>(embed, hattb);
            hatt1_kernel<<<64, 256>>>(hattb);
        }
    }
}

// round 14
// speedup vs baseline: 1.0330x; 1.0330x over previous
#include <cuda_runtime.h>
#include <math.h>

#define Bz 32
#define Hh 512
#define Vv 10000
#define Tt 20
#define Ss 49
#define G4 2048
#define NT_LOG 313          // 32-wide v tiles

// ---------------- device scratch ----------------
__device__ float g_keysT[Bz*Ss*Hh];      // [b][s][d]
__device__ float g_valsSD[Bz*Ss*Hh];     // [b][s][d]
__device__ float g_h[2*Bz*Hh];           // post-cell hidden
__device__ float g_hF[2*Bz*Hh];          // post-attention hidden (recurrent input)
__device__ float g_c[2*Bz*Hh];
__device__ float g_emb[Bz*Hh];
__device__ float g_q[2*Bz*Hh];
__device__ float g_attn[2*Bz*Hh];
__device__ float g_logits[Bz*Vv];
__device__ float g_gpart[8*Bz*G4];       // 8 k-slice partials
__device__ float g_WihP[2*512*G4];       // [l][k][c], c = x*64 + q*4 + gate
__device__ float g_WhhP[2*512*G4];
__device__ float g_projWT[Hh*Vv];        // [d][v]
__device__ float g_WqT[Hh*Hh];           // [k][d]
__device__ float g_hattWT[2*Hh*Hh];      // [k][d]
__device__ int   g_cnt[32];              // zero-init; reset by last arriver

__device__ __forceinline__ float sigm(float x) { return 1.0f / (1.0f + expf(-x)); }

// ================= PREP =================

// projW + Wq + hattW transposes (5776 32x32-tile tasks)
__global__ void prep_transposes(const float* __restrict__ projW, const float* __restrict__ Wq,
                                const float* __restrict__ hattW) {
    __shared__ float tile[32][33];
    int tx = threadIdx.x & 31, ty = threadIdx.x >> 5;
    for (int task = blockIdx.x; task < 5776; task += gridDim.x) {
        const float* src; float* dst; int R, C, bx, by;
        if (task < 5008)      { src = projW;         dst = g_projWT;  R = Vv; C = Hh;   bx = task % 16; by = task / 16; }
        else if (task < 5264) { int u = task - 5008; src = Wq;        dst = g_WqT;     R = Hh; C = Hh;   bx = u % 16; by = u / 16; }
        else                  { int u = task - 5264; src = hattW;     dst = g_hattWT;  R = Hh; C = 2*Hh; bx = u % 32; by = u / 32; }
        for (int i = 0; i < 32; i += 8) {
            int r = by*32 + ty + i, c = bx*32 + tx;
            if (r < R && c < C) tile[ty + i][tx] = src[r*C + c];
        }
        __syncthreads();
        for (int i = 0; i < 32; i += 8) {
            int r = by*32 + tx, c = bx*32 + ty + i;
            if (r < R && c < C) dst[c*R + r] = tile[tx][ty + i];
        }
        __syncthreads();
    }
}

// COALESCED gate-weight reorder. dst[l][k][c], c = x*64 + q*4 + g, src row = g*512 + x*16 + q.
// Block = (part, l, x, ktile): reads 64 rows x 32 k coalesced, writes 32 k x 64 c coalesced.
__global__ __launch_bounds__(256) void prep_reorder(const float* __restrict__ Wih,
                                                    const float* __restrict__ Whh) {
    __shared__ float sm[64][33];
    int blk = blockIdx.x;                 // 2048 = 2part * 2l * 32x * 16kt
    int kt   = blk & 15;
    int x    = (blk >> 4) & 31;
    int l    = (blk >> 9) & 1;
    int part = blk >> 10;
    int k0 = kt * 32;
    const float* src = part ? Whh : Wih;
    float* dst = part ? g_WhhP : g_WihP;
    int tid = threadIdx.x;
#pragma unroll
    for (int i = 0; i < 2048; i += 256) {
        int idx = i + tid;
        int rl = idx >> 5, kk = idx & 31;       // rl = g*16 + q
        int q = rl & 15, g = rl >> 4;
        int row = g*512 + x*16 + q;
        sm[rl][kk] = src[(l*G4 + row)*512 + k0 + kk];
    }
    __syncthreads();
#pragma unroll
    for (int i = 0; i < 2048; i += 256) {
        int idx = i + tid;
        int kk = idx >> 6, cc = idx & 63;       // cc = q*4 + g
        int q = cc >> 2, g = cc & 3;
        int rl = g*16 + q;
        dst[(l*512 + k0 + kk)*G4 + x*64 + cc] = sm[rl][kk];
    }
}

__global__ void prep_kv(const float* __restrict__ chan,
                        const float* __restrict__ Wk, const float* __restrict__ bk,
                        const float* __restrict__ Wv, const float* __restrict__ bv) {
    int id = blockIdx.x * 256 + threadIdx.x;
    int d = id & 511;
    int r = id >> 9;
    int s = r % Ss;
    int b = r / Ss;
    const float* cp  = &chan[(b*Hh + d)*Ss];
    const float* wkp = &Wk[s*Ss];
    const float* wvp = &Wv[s*Ss];
    float aK = bk[s], aV = bv[s];
#pragma unroll
    for (int k = 0; k < Ss; k++) { float c = cp[k]; aK += c*wkp[k]; aV += c*wvp[k]; }
    g_keysT[(b*Ss + s)*Hh + d]  = tanhf(aK);
    g_valsSD[(b*Ss + s)*Hh + d] = tanhf(aV);
}

__global__ void prep_init_t0(const float* __restrict__ pooled, const float* __restrict__ embed,
                             const int* __restrict__ sos, const float* __restrict__ projb,
                             float* __restrict__ res) {
    int blk = blockIdx.x, tid = threadIdx.x;
    if (blk < 40) {
        int v = blk*256 + tid;
        if (v < Vv) {
            int sv = sos[0];
            float acc = projb[v];
            for (int d = 0; d < Hh; d++) acc += embed[sv*Hh + d] * g_projWT[d*Vv + v];
            for (int b = 0; b < Bz; b++) res[b*(Vv*Tt) + v*Tt] = acc;
        }
    } else {
        int i = (blk - 40)*256 + tid;
        int d = i & (Hh - 1);
        g_emb[i] = embed[sos[0]*Hh + d];
        float p = pooled[i];
        g_hF[i] = p; g_hF[Bz*Hh + i] = p;
        g_c[i]  = p; g_c[Bz*Hh + i]  = p;
    }
}

// ================= shared gates + fused cell body =================
__device__ void gatescell_body(int l, const float* __restrict__ bih,
                               const float* __restrict__ bhh, float* S) {
    __shared__ int s_last;
    int tid = threadIdx.x, blk = blockIdx.x;
    int x = blk & 31, y = blk >> 5;          // x: 64-c chunk, y: 128-k slice
    int ihPart = (y < 4);
    int kbase = (y & 3) * 128;
    const float* src = ihPart ? ((l == 0) ? g_emb : g_h) : (g_hF + l*Bz*Hh);
    float* sh = S;                            // [32 b][128 k]
    for (int i = tid; i < 32*128; i += 256) {
        int b = i >> 7, kk = i & 127;
        sh[b*128 + kk] = src[b*Hh + kbase + kk];
    }
    __syncthreads();

    const float* WT = (ihPart ? g_WihP : g_WhhP) + l*512*G4;
    int jl = tid & 63, bg = tid >> 6;
    int j = x*64 + jl;

    float acc0=0,acc1=0,acc2=0,acc3=0,acc4=0,acc5=0,acc6=0,acc7=0;
    const float* shb = &sh[bg*8*128];
#pragma unroll 8
    for (int mi = 0; mi < 128; mi += 4) {
        const float* wp = &WT[(kbase + mi)*G4 + j];
        float w0 = wp[0], w1 = wp[G4], w2 = wp[2*G4], w3 = wp[3*G4];
        float4 v0 = *(const float4*)&shb[0*128 + mi];
        float4 v1 = *(const float4*)&shb[1*128 + mi];
        float4 v2 = *(const float4*)&shb[2*128 + mi];
        float4 v3 = *(const float4*)&shb[3*128 + mi];
        float4 v4 = *(const float4*)&shb[4*128 + mi];
        float4 v5 = *(const float4*)&shb[5*128 + mi];
        float4 v6 = *(const float4*)&shb[6*128 + mi];
        float4 v7 = *(const float4*)&shb[7*128 + mi];
        acc0 += v0.x*w0 + v0.y*w1 + v0.z*w2 + v0.w*w3;
        acc1 += v1.x*w0 + v1.y*w1 + v1.z*w2 + v1.w*w3;
        acc2 += v2.x*w0 + v2.y*w1 + v2.z*w2 + v2.w*w3;
        acc3 += v3.x*w0 + v3.y*w1 + v3.z*w2 + v3.w*w3;
        acc4 += v4.x*w0 + v4.y*w1 + v4.z*w2 + v4.w*w3;
        acc5 += v5.x*w0 + v5.y*w1 + v5.z*w2 + v5.w*w3;
        acc6 += v6.x*w0 + v6.y*w1 + v6.z*w2 + v6.w*w3;
        acc7 += v7.x*w0 + v7.y*w1 + v7.z*w2 + v7.w*w3;
    }
    int bb = bg*8;
    float* gp = &g_gpart[(y*32)*G4 + j];
    gp[(bb+0)*G4] = acc0; gp[(bb+1)*G4] = acc1;
    gp[(bb+2)*G4] = acc2; gp[(bb+3)*G4] = acc3;
    gp[(bb+4)*G4] = acc4; gp[(bb+5)*G4] = acc5;
    gp[(bb+6)*G4] = acc6; gp[(bb+7)*G4] = acc7;

    // ---- last-block fused cell ----
    __threadfence();
    __syncthreads();
    if (tid == 0) {
        int old = atomicAdd(&g_cnt[x], 1);
        s_last = (old == 7) ? 1 : 0;
        if (old == 7) g_cnt[x] = 0;
    }
    __syncthreads();
    if (!s_last) return;
    __threadfence();

    int c_l = tid & 63, bh2 = tid >> 6;
    float tot[8];
#pragma unroll
    for (int j2 = 0; j2 < 8; j2++) tot[j2] = 0.f;
    for (int yy = 0; yy < 8; yy++) {
        const float* gp2 = &g_gpart[(yy*32 + bh2*8)*G4 + x*64 + c_l];
#pragma unroll
        for (int j2 = 0; j2 < 8; j2++) tot[j2] += gp2[j2*G4];
    }
    float* sc = S;
    __syncthreads();
#pragma unroll
    for (int j2 = 0; j2 < 8; j2++) sc[(bh2*8 + j2)*64 + c_l] = tot[j2];
    __syncthreads();
#pragma unroll
    for (int rep = 0; rep < 2; rep++) {
        int idx = rep*256 + tid;
        int q = idx >> 5, b = idx & 31;
        int gi = x*16 + q;
        const float* bi = bih + l*G4; const float* bhp = bhh + l*G4;
        const float* scb = &sc[b*64 + q*4];
        float vi = scb[0] + bi[gi]        + bhp[gi];
        float vf = scb[1] + bi[512 + gi]  + bhp[512 + gi];
        float vg = scb[2] + bi[1024 + gi] + bhp[1024 + gi];
        float vo = scb[3] + bi[1536 + gi] + bhp[1536 + gi];
        int id2 = (l*Bz + b)*Hh + gi;
        float c = g_c[id2];
        float cn = sigm(vf)*c + sigm(vi)*tanhf(vg);
        g_c[id2] = cn;
        g_h[id2] = sigm(vo)*tanhf(cn);
    }
}

// ================= q-GEMM body =================
__device__ void q_body(int l, int qb, float* sH, const float* __restrict__ bq) {
    int tid = threadIdx.x;
    const float4* h4 = (const float4*)(g_h + l*Bz*Hh);
    float4* s4 = (float4*)sH;
    for (int i = tid; i < Bz*Hh/4; i += 256) s4[i] = h4[i];
    __syncthreads();

    int lane = tid & 31, bg = tid >> 5;
    int d = qb*32 + lane;
    float acc0 = 0.f, acc1 = 0.f, acc2 = 0.f, acc3 = 0.f;
    const float* a0 = &sH[(bg*4 + 0)*Hh];
    const float* a1 = &sH[(bg*4 + 1)*Hh];
    const float* a2 = &sH[(bg*4 + 2)*Hh];
    const float* a3 = &sH[(bg*4 + 3)*Hh];
#pragma unroll 8
    for (int k = 0; k < Hh; k += 4) {
        const float* wp = &g_WqT[k*Hh + d];
        float w0 = wp[0], w1 = wp[Hh], w2 = wp[2*Hh], w3 = wp[3*Hh];
        float4 v0 = *(const float4*)&a0[k];
        float4 v1 = *(const float4*)&a1[k];
        float4 v2 = *(const float4*)&a2[k];
        float4 v3 = *(const float4*)&a3[k];
        acc0 += v0.x*w0 + v0.y*w1 + v0.z*w2 + v0.w*w3;
        acc1 += v1.x*w0 + v1.y*w1 + v1.z*w2 + v1.w*w3;
        acc2 += v2.x*w0 + v2.y*w1 + v2.z*w2 + v2.w*w3;
        acc3 += v3.x*w0 + v3.y*w1 + v3.z*w2 + v3.w*w3;
    }
    float bv = bq[d];
    g_q[(l*Bz + bg*4 + 0)*Hh + d] = tanhf(acc0 + bv);
    g_q[(l*Bz + bg*4 + 1)*Hh + d] = tanhf(acc1 + bv);
    g_q[(l*Bz + bg*4 + 2)*Hh + d] = tanhf(acc2 + bv);
    g_q[(l*Bz + bg*4 + 3)*Hh + d] = tanhf(acc3 + bv);
}

// ================= attention body =================
__device__ void att_body(int l, int b0, float* S) {
    int tid = threadIdx.x;
    float* sq   = S;            // [2][512]
    float* ssc  = S + 1024;
    float* sw   = S + 1152;
    float* smax = S + 1280;
    float* sinv = S + 1284;
    for (int i = tid; i < 2*Hh; i += 256) {
        int bb = i >> 9;
        sq[i] = g_q[(l*Bz + b0 + bb)*Hh + (i & 511)];
    }
    __syncthreads();

    int warp = tid >> 5, lane = tid & 31;
    int half = warp >> 2, w2 = warp & 3;
    int b = b0 + half;
    for (int s = w2; s < Ss; s += 4) {
        const float* kp = &g_keysT[(b*Ss + s)*Hh];
        const float* qp = &sq[half*Hh];
        float p = 0.f;
        for (int d = lane; d < Hh; d += 32) p += qp[d]*kp[d];
#pragma unroll
        for (int o = 16; o; o >>= 1) p += __shfl_xor_sync(0xffffffffu, p, o);
        if (lane == 0) ssc[half*64 + s] = p * (1.0f/7.0f);
    }
    __syncthreads();
    if (tid < 2) {
        float mx = -INFINITY;
        for (int s = 0; s < Ss; s++) mx = fmaxf(mx, ssc[tid*64 + s]);
        smax[tid] = mx;
    }
    __syncthreads();
    if (tid < 128) {
        int bb = tid >> 6, s = tid & 63;
        if (s < Ss) sw[bb*64 + s] = expf(ssc[bb*64 + s] - smax[bb]);
    }
    __syncthreads();
    if (tid < 2) {
        float sum = 0.f;
        for (int s = 0; s < Ss; s++) sum += sw[tid*64 + s];
        sinv[tid] = 1.0f / sum;
    }
    __syncthreads();
#pragma unroll
    for (int rep = 0; rep < 4; rep++) {
        int idx = rep*256 + tid;
        int bb = idx >> 9, d = idx & 511;
        const float* wv = &sw[bb*64];
        float a = 0.f;
#pragma unroll
        for (int s = 0; s < Ss; s++)
            a += wv[s] * g_valsSD[((b0 + bb)*Ss + s)*Hh + d];
        g_attn[(l*Bz + b0 + bb)*Hh + d] = a * sinv[bb];
    }
}

// ================= logits body (R12 scalar version) =================
__device__ void logits_body(int tile, float* shl, const float* __restrict__ projb,
                            float* __restrict__ res, int t) {
    int tid = threadIdx.x;
    const float4* H4 = (const float4*)(g_h + Bz*Hh);
    float4* S4 = (float4*)shl;
    for (int i = tid; i < Bz*Hh/4; i += 256) S4[i] = H4[i];
    __syncthreads();

    int vl = tid & 31, bg = tid >> 5;
    int v = tile*32 + vl;
    int vc = (v < Vv) ? v : (Vv - 1);
    bool valid = (v < Vv);

    float acc0=0, acc1=0, acc2=0, acc3=0;
    const float* h0 = &shl[(bg*4 + 0)*Hh];
    const float* h1 = &shl[(bg*4 + 1)*Hh];
    const float* h2 = &shl[(bg*4 + 2)*Hh];
    const float* h3 = &shl[(bg*4 + 3)*Hh];
#pragma unroll 8
    for (int d = 0; d < Hh; d += 4) {
        const float* wp = &g_projWT[d*Vv + vc];
        float w0 = wp[0], w1 = wp[Vv], w2 = wp[2*Vv], w3 = wp[3*Vv];
        float4 a0 = *(const float4*)&h0[d];
        float4 a1 = *(const float4*)&h1[d];
        float4 a2 = *(const float4*)&h2[d];
        float4 a3 = *(const float4*)&h3[d];
        acc0 += a0.x*w0 + a0.y*w1 + a0.z*w2 + a0.w*w3;
        acc1 += a1.x*w0 + a1.y*w1 + a1.z*w2 + a1.w*w3;
        acc2 += a2.x*w0 + a2.y*w1 + a2.z*w2 + a2.w*w3;
        acc3 += a3.x*w0 + a3.y*w1 + a3.z*w2 + a3.w*w3;
    }
    if (valid) {
        float pb = projb[v];
        float a[4] = {acc0, acc1, acc2, acc3};
#pragma unroll
        for (int i = 0; i < 4; i++) {
            int b = bg*4 + i;
            float r = a[i] + pb;
            g_logits[b*Vv + v] = r;
            res[b*(Vv*Tt) + v*Tt + t] = r;
        }
    }
}

// ================= argmax body =================
__device__ void argmax_body(int b, float* S, const float* __restrict__ embed) {
    float* sv = S;
    int* si = (int*)(S + 256);
    int tid = threadIdx.x;
    float best = -INFINITY; int bi = 0;
    for (int v = tid; v < Vv; v += 256) {
        float x = g_logits[b*Vv + v];
        if (x > best) { best = x; bi = v; }
    }
    sv[tid] = best; si[tid] = bi;
    __syncthreads();
    for (int s = 128; s > 0; s >>= 1) {
        if (tid < s) {
            float ov = sv[tid + s]; int oi = si[tid + s];
            if (ov > sv[tid] || (ov == sv[tid] && oi < si[tid])) { sv[tid] = ov; si[tid] = oi; }
        }
        __syncthreads();
    }
    int widx = si[0];
    for (int d = tid; d < Hh; d += 256)
        g_emb[b*Hh + d] = embed[widx*Hh + d];
}

// ================= hatt body =================
__device__ void hatt_body(int l, int rb, float* S, const float* __restrict__ hattb) {
    float* sX = S;               // [8][1024]
    float* sred = S + 8*1024;    // [256][8]
    int tid = threadIdx.x;
    int dg = rb >> 2, bq4 = rb & 3;
    int b0 = bq4*8;
    for (int i = tid; i < 8*1024; i += 256) {
        int b = i >> 10, kk = i & 1023;
        float v = (kk < 512) ? g_attn[(l*Bz + b0 + b)*Hh + kk]
                             : g_h[(l*Bz + b0 + b)*Hh + (kk - 512)];
        sX[i] = v;
    }
    __syncthreads();

    int lane = tid & 31, w = tid >> 5;
    int d = dg*32 + lane;
    float acc[8];
#pragma unroll
    for (int j = 0; j < 8; j++) acc[j] = 0.f;
    int k0 = w*128;
#pragma unroll 2
    for (int kk = k0; kk < k0 + 128; kk += 4) {
        const float* wp = &g_hattWT[kk*Hh + d];
        float w0 = wp[0], w1 = wp[Hh], w2 = wp[2*Hh], w3 = wp[3*Hh];
#pragma unroll
        for (int j = 0; j < 8; j++) {
            float4 a = *(const float4*)&sX[j*1024 + kk];
            acc[j] += a.x*w0 + a.y*w1 + a.z*w2 + a.w*w3;
        }
    }
#pragma unroll
    for (int j = 0; j < 8; j++) sred[(w*32 + lane)*8 + j] = acc[j];
    __syncthreads();

    int d_l = tid >> 3, j = tid & 7;
    float s = 0.f;
#pragma unroll
    for (int w2 = 0; w2 < 8; w2++) s += sred[(w2*32 + d_l)*8 + j];
    int dd = dg*32 + d_l;
    g_hF[(l*Bz + b0 + j)*Hh + dd] = tanhf(s + hattb[dd]);
}

// ================= step kernels =================
__global__ __launch_bounds__(256) void gatescell0_kernel(const float* __restrict__ bih,
                                                         const float* __restrict__ bhh) {
    extern __shared__ float S[];
    gatescell_body(0, bih, bhh, S);
}

// gatescell(l=1) blocks 0..255 || q0 blocks 256..271
__global__ __launch_bounds__(256) void gc1_q0_kernel(const float* __restrict__ bih,
                                                     const float* __restrict__ bhh,
                                                     const float* __restrict__ bq) {
    extern __shared__ float S[];
    int blk = blockIdx.x;
    if (blk < 256) gatescell_body(1, bih, bhh, S);
    else           q_body(0, blk - 256, S, bq);
}

// logits blocks 0..312 || q1 blocks 313..328 || att0 blocks 329..344
__global__ __launch_bounds__(256) void logits_q1_att0_kernel(const float* __restrict__ projb,
                                                             float* __restrict__ res, int t,
                                                             const float* __restrict__ bq) {
    extern __shared__ float S[];
    int blk = blockIdx.x;
    if (blk < NT_LOG)           logits_body(blk, S, projb, res, t);
    else if (blk < NT_LOG + 16) q_body(1, blk - NT_LOG, S, bq);
    else                        att_body(0, (blk - NT_LOG - 16)*2, S);
}

// att1 blocks 0..15 || argmax blocks 16..47 || hatt0 blocks 48..111
__global__ __launch_bounds__(256) void att1_argmax_hatt0_kernel(const float* __restrict__ embed,
                                                                const float* __restrict__ hattb) {
    __shared__ float SS[8*1024 + 256*8];    // 40 KB
    int blk = blockIdx.x;
    if (blk < 16)      att_body(1, blk*2, SS);
    else if (blk < 48) argmax_body(blk - 16, SS, embed);
    else               hatt_body(0, blk - 48, SS, hattb);
}

__global__ __launch_bounds__(256) void hatt1_kernel(const float* __restrict__ hattb) {
    __shared__ float SS[8*1024 + 256*8];
    hatt_body(1, blockIdx.x, SS, hattb);
}

// ---------------- host launcher ----------------
extern "C" void kernel_launch(void* const* d_in, const int* in_sizes, int n_in,
                              void* d_out, int out_size) {
    const float* img    = (const float*)d_in[0];
    const float* pooled = (const float*)d_in[1];
    const float* embed  = (const float*)d_in[2];
    const float* Wq     = (const float*)d_in[3];
    const float* bq     = (const float*)d_in[4];
    const float* Wk     = (const float*)d_in[5];
    const float* bk     = (const float*)d_in[6];
    const float* Wv     = (const float*)d_in[7];
    const float* bv     = (const float*)d_in[8];
    const float* Wih    = (const float*)d_in[9];
    const float* Whh    = (const float*)d_in[10];
    const float* bih    = (const float*)d_in[11];
    const float* bhh    = (const float*)d_in[12];
    const float* projW  = (const float*)d_in[13];
    const float* projb  = (const float*)d_in[14];
    const float* hattW  = (const float*)d_in[15];
    const float* hattb  = (const float*)d_in[16];
    const int*   sos    = (const int*)d_in[17];
    float* res = (float*)d_out;

    const int big_smem = Bz * Hh * (int)sizeof(float);   // 64 KB
    cudaFuncSetAttribute(gatescell0_kernel,     cudaFuncAttributeMaxDynamicSharedMemorySize, big_smem);
    cudaFuncSetAttribute(gc1_q0_kernel,         cudaFuncAttributeMaxDynamicSharedMemorySize, big_smem);
    cudaFuncSetAttribute(logits_q1_att0_kernel, cudaFuncAttributeMaxDynamicSharedMemorySize, big_smem);

    prep_transposes<<<592, 256>>>(projW, Wq, hattW);
    prep_reorder<<<2048, 256>>>(Wih, Whh);
    prep_kv<<<3136, 256>>>(img, Wk, bk, Wv, bv);
    prep_init_t0<<<104, 256>>>(pooled, embed, sos, projb, res);

    const int gate_smem = 32 * 128 * (int)sizeof(float);  // 16 KB
    for (int t = 0; t < Tt - 1; t++) {
        int withQ = (t < Tt - 2) ? 1 : 0;
        gatescell0_kernel<<<256, 256, gate_smem>>>(bih, bhh);
        if (withQ) gc1_q0_kernel<<<272, 256, big_smem>>>(bih, bhh, bq);
        else       gc1_q0_kernel<<<256, 256, gate_smem>>>(bih, bhh, bq);
        logits_q1_att0_kernel<<<withQ ? (NT_LOG + 32) : NT_LOG, 256, big_smem>>>(projb, res, t + 1, bq);
        if (withQ) {
            att1_argmax_hatt0_kernel<<<112, 256>>>(embed, hattb);
            hatt1_kernel<<<64, 256>>>(hattb);
        }
    }
}

// round 15
// speedup vs baseline: 1.3846x; 1.3404x over previous
#include <cuda_runtime.h>
#include <math.h>

#define Bz 32
#define Hh 512
#define Vv 10000
#define Tt 20
#define Ss 49
#define G4 2048
#define NT_LOG 626          // 32v x 16b tiles

// ---------------- device scratch ----------------
__device__ float g_keysT[Bz*Ss*Hh];      // [b][s][d]
__device__ float g_valsSD[Bz*Ss*Hh];     // [b][s][d]
__device__ float g_h[2*Bz*Hh];           // post-cell hidden
__device__ float g_hF[2*Bz*Hh];          // post-attention hidden (recurrent input)
__device__ float g_c[2*Bz*Hh];
__device__ float g_emb[Bz*Hh];
__device__ float g_q[2*Bz*Hh];
__device__ float g_attn[2*Bz*Hh];
__device__ float g_logits[Bz*Vv];
__device__ float g_gpart[8*Bz*G4];       // 8 k-slice partials
__device__ float g_WihT[2*Hh*G4];        // [l][k][j]
__device__ float g_WhhT[2*Hh*G4];
__device__ float g_projWT[Hh*Vv];        // [d][v]
__device__ float g_WqT[Hh*Hh];           // [k][d]
__device__ float g_hattWT[2*Hh*Hh];      // [k][d]

__device__ __forceinline__ float sigm(float x) { return 1.0f / (1.0f + expf(-x)); }

// ================= PREP (R12 versions) =================

__global__ void prep_transposes(const float* __restrict__ projW, const float* __restrict__ Wih,
                                const float* __restrict__ Whh,  const float* __restrict__ Wq,
                                const float* __restrict__ hattW) {
    __shared__ float tile[32][33];
    int tx = threadIdx.x & 31, ty = threadIdx.x >> 5;
    for (int task = blockIdx.x; task < 9872; task += gridDim.x) {
        const float* src; float* dst; int R, C, bx, by;
        if (task < 5008)      { src = projW;         dst = g_projWT;       R = Vv; C = Hh;  bx = task % 16; by = task / 16; }
        else if (task < 6032) { int u = task - 5008; src = Wih;            dst = g_WihT;         R = G4; C = Hh;  bx = u % 16; by = u / 16; }
        else if (task < 7056) { int u = task - 6032; src = Wih + G4*Hh;    dst = g_WihT + Hh*G4; R = G4; C = Hh;  bx = u % 16; by = u / 16; }
        else if (task < 8080) { int u = task - 7056; src = Whh;            dst = g_WhhT;         R = G4; C = Hh;  bx = u % 16; by = u / 16; }
        else if (task < 9104) { int u = task - 8080; src = Whh + G4*Hh;    dst = g_WhhT + Hh*G4; R = G4; C = Hh;  bx = u % 16; by = u / 16; }
        else if (task < 9360) { int u = task - 9104; src = Wq;             dst = g_WqT;          R = Hh; C = Hh;  bx = u % 16; by = u / 16; }
        else                  { int u = task - 9360; src = hattW;          dst = g_hattWT;       R = Hh; C = 2*Hh; bx = u % 32; by = u / 32; }
        for (int i = 0; i < 32; i += 8) {
            int r = by*32 + ty + i, c = bx*32 + tx;
            if (r < R && c < C) tile[ty + i][tx] = src[r*C + c];
        }
        __syncthreads();
        for (int i = 0; i < 32; i += 8) {
            int r = by*32 + tx, c = bx*32 + ty + i;
            if (r < R && c < C) dst[c*R + r] = tile[tx][ty + i];
        }
        __syncthreads();
    }
}

__global__ void prep_kv(const float* __restrict__ chan,
                        const float* __restrict__ Wk, const float* __restrict__ bk,
                        const float* __restrict__ Wv, const float* __restrict__ bv) {
    int id = blockIdx.x * 256 + threadIdx.x;
    int d = id & 511;
    int r = id >> 9;
    int s = r % Ss;
    int b = r / Ss;
    const float* cp  = &chan[(b*Hh + d)*Ss];
    const float* wkp = &Wk[s*Ss];
    const float* wvp = &Wv[s*Ss];
    float aK = bk[s], aV = bv[s];
#pragma unroll
    for (int k = 0; k < Ss; k++) { float c = cp[k]; aK += c*wkp[k]; aV += c*wvp[k]; }
    g_keysT[(b*Ss + s)*Hh + d]  = tanhf(aK);
    g_valsSD[(b*Ss + s)*Hh + d] = tanhf(aV);
}

__global__ void prep_init_t0(const float* __restrict__ pooled, const float* __restrict__ embed,
                             const int* __restrict__ sos, const float* __restrict__ projb,
                             float* __restrict__ res) {
    int blk = blockIdx.x, tid = threadIdx.x;
    if (blk < 40) {
        int v = blk*256 + tid;
        if (v < Vv) {
            int sv = sos[0];
            float acc = projb[v];
            for (int d = 0; d < Hh; d++) acc += embed[sv*Hh + d] * g_projWT[d*Vv + v];
            for (int b = 0; b < Bz; b++) res[b*(Vv*Tt) + v*Tt] = acc;
        }
    } else {
        int i = (blk - 40)*256 + tid;
        int d = i & (Hh - 1);
        g_emb[i] = embed[sos[0]*Hh + d];
        float p = pooled[i];
        g_hF[i] = p; g_hF[Bz*Hh + i] = p;
        g_c[i]  = p; g_c[Bz*Hh + i]  = p;
    }
}

// ================= gates: 512 blocks (64 j-chunks of 32 x 8 k-slices) =================
__device__ void gates_body(int l, int blk, float* S) {
    int tid = threadIdx.x;
    int x = blk & 63, y = blk >> 6;          // x: 32-j chunk, y: 128-k slice
    int ihPart = (y < 4);
    int kbase = (y & 3) * 128;
    const float* src = ihPart ? ((l == 0) ? g_emb : g_h) : (g_hF + l*Bz*Hh);
    float* sh = S;                            // [32 b][128 k]
    for (int i = tid; i < 32*128; i += 256) {
        int b = i >> 7, kk = i & 127;
        sh[b*128 + kk] = src[b*Hh + kbase + kk];
    }
    __syncthreads();

    const float* WT = (ihPart ? g_WihT : g_WhhT) + l*Hh*G4;
    int jl = tid & 31, bg = tid >> 5;        // 8 groups x 4 batches
    int j = x*32 + jl;

    float acc0=0, acc1=0, acc2=0, acc3=0;
    const float* shb = &sh[bg*4*128];
#pragma unroll 8
    for (int mi = 0; mi < 128; mi += 4) {
        const float* wp = &WT[(kbase + mi)*G4 + j];
        float w0 = wp[0], w1 = wp[G4], w2 = wp[2*G4], w3 = wp[3*G4];
        float4 v0 = *(const float4*)&shb[0*128 + mi];
        float4 v1 = *(const float4*)&shb[1*128 + mi];
        float4 v2 = *(const float4*)&shb[2*128 + mi];
        float4 v3 = *(const float4*)&shb[3*128 + mi];
        acc0 += v0.x*w0 + v0.y*w1 + v0.z*w2 + v0.w*w3;
        acc1 += v1.x*w0 + v1.y*w1 + v1.z*w2 + v1.w*w3;
        acc2 += v2.x*w0 + v2.y*w1 + v2.z*w2 + v2.w*w3;
        acc3 += v3.x*w0 + v3.y*w1 + v3.z*w2 + v3.w*w3;
    }
    float* gp = &g_gpart[(y*32 + bg*4)*G4 + j];
    gp[0]      = acc0;
    gp[G4]     = acc1;
    gp[2*G4]   = acc2;
    gp[3*G4]   = acc3;
}

__global__ __launch_bounds__(256) void gates0_kernel() {
    extern __shared__ float S[];
    gates_body(0, blockIdx.x, S);
}

// ================= q-GEMM (16-batch halves, 32KB smem): 32 blocks/layer =================
__device__ void q_body(int l, int qb, float* sH, const float* __restrict__ bq) {
    int tid = threadIdx.x;
    int dchunk = qb & 15, bhalf = qb >> 4;
    const float4* h4 = (const float4*)(g_h + (l*Bz + bhalf*16)*Hh);
    float4* s4 = (float4*)sH;
    for (int i = tid; i < 16*Hh/4; i += 256) s4[i] = h4[i];
    __syncthreads();

    int lane = tid & 31, bg = tid >> 5;      // 8 groups x 2 batches
    int d = dchunk*32 + lane;
    float acc0 = 0.f, acc1 = 0.f;
    const float* a0 = &sH[(bg*2 + 0)*Hh];
    const float* a1 = &sH[(bg*2 + 1)*Hh];
#pragma unroll 8
    for (int k = 0; k < Hh; k += 4) {
        const float* wp = &g_WqT[k*Hh + d];
        float w0 = wp[0], w1 = wp[Hh], w2 = wp[2*Hh], w3 = wp[3*Hh];
        float4 v0 = *(const float4*)&a0[k];
        float4 v1 = *(const float4*)&a1[k];
        acc0 += v0.x*w0 + v0.y*w1 + v0.z*w2 + v0.w*w3;
        acc1 += v1.x*w0 + v1.y*w1 + v1.z*w2 + v1.w*w3;
    }
    float bv = bq[d];
    g_q[(l*Bz + bhalf*16 + bg*2 + 0)*Hh + d] = tanhf(acc0 + bv);
    g_q[(l*Bz + bhalf*16 + bg*2 + 1)*Hh + d] = tanhf(acc1 + bv);
}

// gates(l=1) blocks 0..511 || q0 blocks 512..543
__global__ __launch_bounds__(256) void gates1_q0_kernel(const float* __restrict__ bq) {
    extern __shared__ float S[];
    int blk = blockIdx.x;
    if (blk < 512) gates_body(1, blk, S);
    else           q_body(0, blk - 512, S, bq);
}

// ================= cell: sum 8 partials (R12 verbatim) =================
__global__ void cell_kernel(int l, const float* __restrict__ bih,
                            const float* __restrict__ bhh) {
    int b = blockIdx.x, j = threadIdx.x;
    const float* bi = &bih[l * G4];
    const float* bh = &bhh[l * G4];
    float gi = bi[j]        + bh[j];
    float gf = bi[512 + j]  + bh[512 + j];
    float gg = bi[1024 + j] + bh[1024 + j];
    float go = bi[1536 + j] + bh[1536 + j];
#pragma unroll
    for (int ks = 0; ks < 8; ks++) {
        const float* gp = &g_gpart[(ks * 32 + b) * G4];
        gi += gp[j]; gf += gp[512 + j]; gg += gp[1024 + j]; go += gp[1536 + j];
    }
    int idx = (l * Bz + b) * Hh + j;
    float c  = g_c[idx];
    float cn = sigm(gf) * c + sigm(gi) * tanhf(gg);
    g_c[idx] = cn;
    g_h[idx] = sigm(go) * tanhf(cn);
}

// ================= logits: 626 tiles of 32v x 16b, 32KB smem =================
__device__ void logits_body(int tl, float* shl, const float* __restrict__ projb,
                            float* __restrict__ res, int t) {
    int tid = threadIdx.x;
    int bhalf = tl & 1;
    int vt = tl >> 1;
    const float4* H4 = (const float4*)(g_h + (Bz + bhalf*16)*Hh);  // layer-1, batch half
    float4* S4 = (float4*)shl;
    for (int i = tid; i < 16*Hh/4; i += 256) S4[i] = H4[i];
    __syncthreads();

    int vl = tid & 31, bg = tid >> 5;        // 8 groups x 2 batches
    int v = vt*32 + vl;
    int vc = (v < Vv) ? v : (Vv - 1);

    float acc0=0, acc1=0;
    const float* h0 = &shl[(bg*2 + 0)*Hh];
    const float* h1 = &shl[(bg*2 + 1)*Hh];
#pragma unroll 8
    for (int d = 0; d < Hh; d += 4) {
        const float* wp = &g_projWT[d*Vv + vc];
        float w0 = wp[0], w1 = wp[Vv], w2 = wp[2*Vv], w3 = wp[3*Vv];
        float4 a0 = *(const float4*)&h0[d];
        float4 a1 = *(const float4*)&h1[d];
        acc0 += a0.x*w0 + a0.y*w1 + a0.z*w2 + a0.w*w3;
        acc1 += a1.x*w0 + a1.y*w1 + a1.z*w2 + a1.w*w3;
    }
    if (v < Vv) {
        float pb = projb[v];
        float a[2] = {acc0, acc1};
#pragma unroll
        for (int i = 0; i < 2; i++) {
            int b = bhalf*16 + bg*2 + i;
            float r = a[i] + pb;
            g_logits[b*Vv + v] = r;
            res[b*(Vv*Tt) + v*Tt + t] = r;
        }
    }
}

// logits blocks 0..625 || q1 blocks 626..657 || att0 blocks 658..673
__device__ void att_body(int l, int b0, float* S);
__global__ __launch_bounds__(256) void logits_q1_att0_kernel(const float* __restrict__ projb,
                                                             float* __restrict__ res, int t,
                                                             const float* __restrict__ bq) {
    extern __shared__ float S[];
    int blk = blockIdx.x;
    if (blk < NT_LOG)           logits_body(blk, S, projb, res, t);
    else if (blk < NT_LOG + 32) q_body(1, blk - NT_LOG, S, bq);
    else                        att_body(0, (blk - NT_LOG - 32)*2, S);
}

// ================= attention body (2 batches) =================
__device__ void att_body(int l, int b0, float* S) {
    int tid = threadIdx.x;
    float* sq   = S;            // [2][512]
    float* ssc  = S + 1024;
    float* sw   = S + 1152;
    float* smax = S + 1280;
    float* sinv = S + 1284;
    for (int i = tid; i < 2*Hh; i += 256) {
        int bb = i >> 9;
        sq[i] = g_q[(l*Bz + b0 + bb)*Hh + (i & 511)];
    }
    __syncthreads();

    int warp = tid >> 5, lane = tid & 31;
    int half = warp >> 2, w2 = warp & 3;
    int b = b0 + half;
    for (int s = w2; s < Ss; s += 4) {
        const float* kp = &g_keysT[(b*Ss + s)*Hh];
        const float* qp = &sq[half*Hh];
        float p = 0.f;
        for (int d = lane; d < Hh; d += 32) p += qp[d]*kp[d];
#pragma unroll
        for (int o = 16; o; o >>= 1) p += __shfl_xor_sync(0xffffffffu, p, o);
        if (lane == 0) ssc[half*64 + s] = p * (1.0f/7.0f);
    }
    __syncthreads();
    if (tid < 2) {
        float mx = -INFINITY;
        for (int s = 0; s < Ss; s++) mx = fmaxf(mx, ssc[tid*64 + s]);
        smax[tid] = mx;
    }
    __syncthreads();
    if (tid < 128) {
        int bb = tid >> 6, s = tid & 63;
        if (s < Ss) sw[bb*64 + s] = expf(ssc[bb*64 + s] - smax[bb]);
    }
    __syncthreads();
    if (tid < 2) {
        float sum = 0.f;
        for (int s = 0; s < Ss; s++) sum += sw[tid*64 + s];
        sinv[tid] = 1.0f / sum;
    }
    __syncthreads();
#pragma unroll
    for (int rep = 0; rep < 4; rep++) {
        int idx = rep*256 + tid;
        int bb = idx >> 9, d = idx & 511;
        const float* wv = &sw[bb*64];
        float a = 0.f;
#pragma unroll
        for (int s = 0; s < Ss; s++)
            a += wv[s] * g_valsSD[((b0 + bb)*Ss + s)*Hh + d];
        g_attn[(l*Bz + b0 + bb)*Hh + d] = a * sinv[bb];
    }
}

// ================= att1 + argmax (R12 structure, grid 64) =================
__global__ __launch_bounds__(256) void att_argmax_kernel(const float* __restrict__ embed) {
    __shared__ float SS[1344];
    __shared__ float sv[256];
    __shared__ int   si[256];
    int tid = threadIdx.x, blk = blockIdx.x;
    if (blk < 16) {
        att_body(1, blk*2, SS);
    } else if (blk < 48) {
        int b = blk - 16;
        float best = -INFINITY; int bi = 0;
        for (int v = tid; v < Vv; v += 256) {
            float x = g_logits[b*Vv + v];
            if (x > best) { best = x; bi = v; }
        }
        sv[tid] = best; si[tid] = bi;
        __syncthreads();
        for (int s = 128; s > 0; s >>= 1) {
            if (tid < s) {
                float ov = sv[tid + s]; int oi = si[tid + s];
                if (ov > sv[tid] || (ov == sv[tid] && oi < si[tid])) { sv[tid] = ov; si[tid] = oi; }
            }
            __syncthreads();
        }
        int widx = si[0];
        for (int d = tid; d < Hh; d += 256)
            g_emb[b*Hh + d] = embed[widx*Hh + d];
    }
}

// ================= hatt (R12 body, grid 128) =================
__global__ __launch_bounds__(256) void hatt_kernel(const float* __restrict__ hattb) {
    __shared__ float sX[8*1024];
    __shared__ float sred[256*8];
    int tid = threadIdx.x, blk = blockIdx.x;
    int l = blk >> 6, rb = blk & 63;
    int dg = rb >> 2, bq4 = rb & 3;
    int b0 = bq4*8;
    for (int i = tid; i < 8*1024; i += 256) {
        int b = i >> 10, kk = i & 1023;
        float v = (kk < 512) ? g_attn[(l*Bz + b0 + b)*Hh + kk]
                             : g_h[(l*Bz + b0 + b)*Hh + (kk - 512)];
        sX[i] = v;
    }
    __syncthreads();

    int lane = tid & 31, w = tid >> 5;
    int d = dg*32 + lane;
    float acc[8];
#pragma unroll
    for (int j = 0; j < 8; j++) acc[j] = 0.f;
    int k0 = w*128;
#pragma unroll 2
    for (int kk = k0; kk < k0 + 128; kk += 4) {
        const float* wp = &g_hattWT[kk*Hh + d];
        float w0 = wp[0], w1 = wp[Hh], w2 = wp[2*Hh], w3 = wp[3*Hh];
#pragma unroll
        for (int j = 0; j < 8; j++) {
            float4 a = *(const float4*)&sX[j*1024 + kk];
            acc[j] += a.x*w0 + a.y*w1 + a.z*w2 + a.w*w3;
        }
    }
#pragma unroll
    for (int j = 0; j < 8; j++) sred[(w*32 + lane)*8 + j] = acc[j];
    __syncthreads();

    int d_l = tid >> 3, j = tid & 7;
    float s = 0.f;
#pragma unroll
    for (int w2 = 0; w2 < 8; w2++) s += sred[(w2*32 + d_l)*8 + j];
    int dd = dg*32 + d_l;
    g_hF[(l*Bz + b0 + j)*Hh + dd] = tanhf(s + hattb[dd]);
}

// ---------------- host launcher ----------------
extern "C" void kernel_launch(void* const* d_in, const int* in_sizes, int n_in,
                              void* d_out, int out_size) {
    const float* img    = (const float*)d_in[0];
    const float* pooled = (const float*)d_in[1];
    const float* embed  = (const float*)d_in[2];
    const float* Wq     = (const float*)d_in[3];
    const float* bq     = (const float*)d_in[4];
    const float* Wk     = (const float*)d_in[5];
    const float* bk     = (const float*)d_in[6];
    const float* Wv     = (const float*)d_in[7];
    const float* bv     = (const float*)d_in[8];
    const float* Wih    = (const float*)d_in[9];
    const float* Whh    = (const float*)d_in[10];
    const float* bih    = (const float*)d_in[11];
    const float* bhh    = (const float*)d_in[12];
    const float* projW  = (const float*)d_in[13];
    const float* projb  = (const float*)d_in[14];
    const float* hattW  = (const float*)d_in[15];
    const float* hattb  = (const float*)d_in[16];
    const int*   sos    = (const int*)d_in[17];
    float* res = (float*)d_out;

    const int half_smem = 16 * Hh * (int)sizeof(float);   // 32 KB
    const int gate_smem = 32 * 128 * (int)sizeof(float);  // 16 KB

    prep_transposes<<<592, 256>>>(projW, Wih, Whh, Wq, hattW);
    prep_kv<<<3136, 256>>>(img, Wk, bk, Wv, bv);
    prep_init_t0<<<104, 256>>>(pooled, embed, sos, projb, res);

    for (int t = 0; t < Tt - 1; t++) {
        int withQ = (t < Tt - 2) ? 1 : 0;
        gates0_kernel<<<512, 256, gate_smem>>>();
        cell_kernel<<<Bz, Hh>>>(0, bih, bhh);
        if (withQ) gates1_q0_kernel<<<544, 256, half_smem>>>(bq);
        else       gates1_q0_kernel<<<512, 256, gate_smem>>>(bq);
        cell_kernel<<<Bz, Hh>>>(1, bih, bhh);
        logits_q1_att0_kernel<<<withQ ? 674 : NT_LOG, 256, half_smem>>>(projb, res, t + 1, bq);
        if (withQ) {
            att_argmax_kernel<<<48, 256>>>(embed);
            hatt_kernel<<<128, 256>>>(hattb);
        }
    }
}